// round 2
// baseline (speedup 1.0000x reference)
#include <cuda_runtime.h>
#include <math.h>

#define BB 8
#define NN 2048
#define DD 128
#define KK 64
#define TT 128   // descriptor rows per block

// Accumulators (scratch): P[b][k][d] and s[b][k]
__device__ float g_P[BB * KK * DD];
__device__ float g_s[BB * KK];

// ---------------------------------------------------------------------------
// Kernel 0: zero accumulators (graph replays require re-zeroing every launch)
// ---------------------------------------------------------------------------
__global__ void nv_zero() {
    int i = blockIdx.x * blockDim.x + threadIdx.x;
    if (i < BB * KK * DD) g_P[i] = 0.f;
    if (i < BB * KK)      g_s[i] = 0.f;
}

// ---------------------------------------------------------------------------
// Kernel 1: per 128-row tile — normalize, GEMM1 (Xn*C^T), softmax,
//           GEMM2 (A^T*Xn), atomic accumulate
// smem layout (floats):
//   Ct  [128][68]  : centroids transposed (d-major), padded
//   xs  [128][128] : normalized descriptors
//   As  [128][64]  : softmax assignments
//   cn2 [64]       : ||c_k||^2
// ---------------------------------------------------------------------------
__global__ __launch_bounds__(256, 1)
void nv_main(const float* __restrict__ x, const float* __restrict__ cent) {
    extern __shared__ float sm[];
    float* Ct  = sm;                      // 128*68 = 8704
    float* xs  = sm + 128 * 68;           // 16384
    float* As  = xs + 128 * 128;          // 8192
    float* cn2 = As + 128 * 64;           // 64

    const int tid = threadIdx.x;
    const int b   = blockIdx.y;
    const int n0  = blockIdx.x * TT;

    if (tid < KK) cn2[tid] = 0.f;
    __syncthreads();

    // ---- load centroids (transposed) + accumulate cn2 ----
    {
        const float4* c4 = (const float4*)cent;
        #pragma unroll
        for (int i = tid; i < KK * DD / 4; i += 256) {
            float4 v = c4[i];
            int k  = i >> 5;        // row (centroid index)
            int d  = (i & 31) * 4;  // dim
            Ct[(d + 0) * 68 + k] = v.x;
            Ct[(d + 1) * 68 + k] = v.y;
            Ct[(d + 2) * 68 + k] = v.z;
            Ct[(d + 3) * 68 + k] = v.w;
            atomicAdd(&cn2[k], v.x * v.x + v.y * v.y + v.z * v.z + v.w * v.w);
        }
    }

    // ---- load x tile + per-row L2 normalize (warp w handles rows 16w..16w+15) ----
    {
        const int w = tid >> 5, l = tid & 31;
        const float4* x4 = (const float4*)(x + ((size_t)b * NN + n0) * DD);
        float4* xs4w = (float4*)xs;
        for (int r = w * 16; r < w * 16 + 16; r++) {
            float4 v = x4[r * 32 + l];
            float ss = v.x * v.x + v.y * v.y + v.z * v.z + v.w * v.w;
            #pragma unroll
            for (int o = 16; o > 0; o >>= 1)
                ss += __shfl_xor_sync(0xffffffffu, ss, o);
            float rinv = 1.0f / fmaxf(sqrtf(ss), 1e-12f);
            float4 o4 = make_float4(v.x * rinv, v.y * rinv, v.z * rinv, v.w * rinv);
            xs4w[r * 32 + l] = o4;
        }
    }
    __syncthreads();

    const float4* xs4 = (const float4*)xs;

    // ---- GEMM1: acc[i][j] = dot(xn[row_i], c[col_j]) ----
    // thread (tm, tn): rows tm*8..+7, cols tn*4..+3
    const int tm = tid >> 4, tn = tid & 15;

    float acc[8][4];
    #pragma unroll
    for (int i = 0; i < 8; i++)
        #pragma unroll
        for (int j = 0; j < 4; j++) acc[i][j] = 0.f;

    for (int kk4 = 0; kk4 < 32; kk4++) {
        float aa[8][4];
        #pragma unroll
        for (int i = 0; i < 8; i++) {
            float4 v = xs4[(tm * 8 + i) * 32 + kk4];
            aa[i][0] = v.x; aa[i][1] = v.y; aa[i][2] = v.z; aa[i][3] = v.w;
        }
        float bb[4][4];
        #pragma unroll
        for (int q = 0; q < 4; q++) {
            float4 v = *(const float4*)&Ct[(kk4 * 4 + q) * 68 + tn * 4];
            bb[q][0] = v.x; bb[q][1] = v.y; bb[q][2] = v.z; bb[q][3] = v.w;
        }
        #pragma unroll
        for (int i = 0; i < 8; i++)
            #pragma unroll
            for (int j = 0; j < 4; j++)
                #pragma unroll
                for (int q = 0; q < 4; q++)
                    acc[i][j] += aa[i][q] * bb[q][j];
    }

    // ---- softmax over k per row: dist = cn2[k] - 2*S (||xn||^2 shift drops) ----
    {
        float cc[4];
        #pragma unroll
        for (int j = 0; j < 4; j++) cc[j] = cn2[tn * 4 + j];

        float4* A4 = (float4*)As;
        #pragma unroll
        for (int i = 0; i < 8; i++) {
            float dj[4];
            float m = -1e30f;
            #pragma unroll
            for (int j = 0; j < 4; j++) {
                dj[j] = cc[j] - 2.f * acc[i][j];
                m = fmaxf(m, dj[j]);
            }
            #pragma unroll
            for (int o = 8; o > 0; o >>= 1)
                m = fmaxf(m, __shfl_xor_sync(0xffffffffu, m, o, 16));
            float s = 0.f;
            #pragma unroll
            for (int j = 0; j < 4; j++) {
                float e = __expf(dj[j] - m);
                dj[j] = e; s += e;
            }
            #pragma unroll
            for (int o = 8; o > 0; o >>= 1)
                s += __shfl_xor_sync(0xffffffffu, s, o, 16);
            float r = 1.f / s;
            A4[(tm * 8 + i) * 16 + tn] =
                make_float4(dj[0] * r, dj[1] * r, dj[2] * r, dj[3] * r);
        }
    }
    __syncthreads();

    // ---- GEMM2: p[j][q] = sum_t A[t][k_j] * xn[t][d_q] ----
    // thread (tk, td): k = tk*4..+3, d = td*8..+7
    const int tk = tm, td = tn;
    float p[4][8];
    #pragma unroll
    for (int j = 0; j < 4; j++)
        #pragma unroll
        for (int q = 0; q < 8; q++) p[j][q] = 0.f;
    float sl[4] = {0.f, 0.f, 0.f, 0.f};

    const float4* A4 = (const float4*)As;
    for (int t = 0; t < TT; t++) {
        float4 av = A4[t * 16 + tk];
        float4 b0 = xs4[t * 32 + td * 2];
        float4 b1 = xs4[t * 32 + td * 2 + 1];
        float av4[4] = {av.x, av.y, av.z, av.w};
        float bbv[8] = {b0.x, b0.y, b0.z, b0.w, b1.x, b1.y, b1.z, b1.w};
        #pragma unroll
        for (int j = 0; j < 4; j++) sl[j] += av4[j];
        #pragma unroll
        for (int j = 0; j < 4; j++)
            #pragma unroll
            for (int q = 0; q < 8; q++)
                p[j][q] += av4[j] * bbv[q];
    }

    // ---- accumulate into global P, s ----
    float* Pb = g_P + b * KK * DD;
    #pragma unroll
    for (int j = 0; j < 4; j++) {
        int k = tk * 4 + j;
        #pragma unroll
        for (int q = 0; q < 8; q++)
            atomicAdd(&Pb[k * DD + td * 8 + q], p[j][q]);
    }
    if (td == 0) {
        #pragma unroll
        for (int j = 0; j < 4; j++)
            atomicAdd(&g_s[b * KK + tk * 4 + j], sl[j]);
    }
}

// ---------------------------------------------------------------------------
// Kernel 2: finalize — vlad = P - s*c, intra-norm per k, global norm, write out
// ---------------------------------------------------------------------------
__global__ __launch_bounds__(512, 1)
void nv_fin(const float* __restrict__ cent, float* __restrict__ out) {
    __shared__ float V[KK * DD];   // 32KB
    __shared__ float ssm[KK];
    __shared__ float gss;

    const int b = blockIdx.x;
    const int tid = threadIdx.x, w = tid >> 5, l = tid & 31;

    if (tid < KK) ssm[tid] = g_s[b * KK + tid];
    if (tid == 0) gss = 0.f;
    __syncthreads();

    const float4* P4 = (const float4*)(g_P + b * KK * DD);
    const float4* c4 = (const float4*)cent;
    float4* V4 = (float4*)V;

    float gloc = 0.f;
    #pragma unroll
    for (int kk = 0; kk < 4; kk++) {
        int k = w * 4 + kk;
        float4 pv = P4[k * 32 + l];
        float4 cv = c4[k * 32 + l];
        float sk = ssm[k];
        float4 v = make_float4(pv.x - sk * cv.x, pv.y - sk * cv.y,
                               pv.z - sk * cv.z, pv.w - sk * cv.w);
        float ss = v.x * v.x + v.y * v.y + v.z * v.z + v.w * v.w;
        #pragma unroll
        for (int o = 16; o > 0; o >>= 1)
            ss += __shfl_xor_sync(0xffffffffu, ss, o);
        float rinv = 1.f / fmaxf(sqrtf(ss), 1e-12f);
        v.x *= rinv; v.y *= rinv; v.z *= rinv; v.w *= rinv;
        V4[k * 32 + l] = v;
        gloc += v.x * v.x + v.y * v.y + v.z * v.z + v.w * v.w;
    }
    #pragma unroll
    for (int o = 16; o > 0; o >>= 1)
        gloc += __shfl_xor_sync(0xffffffffu, gloc, o);
    if (l == 0) atomicAdd(&gss, gloc);
    __syncthreads();

    float ginv = 1.f / fmaxf(sqrtf(gss), 1e-12f);
    float4* out4 = (float4*)(out + (size_t)b * KK * DD);
    #pragma unroll
    for (int kk = 0; kk < 4; kk++) {
        int k = w * 4 + kk;
        float4 v = V4[k * 32 + l];
        v.x *= ginv; v.y *= ginv; v.z *= ginv; v.w *= ginv;
        out4[k * 32 + l] = v;
    }
}

// ---------------------------------------------------------------------------
extern "C" void kernel_launch(void* const* d_in, const int* in_sizes, int n_in,
                              void* d_out, int out_size) {
    const float* x    = (const float*)d_in[0];
    const float* cent = (const float*)d_in[1];
    float* out        = (float*)d_out;

    const size_t smem = (size_t)(128 * 68 + 128 * 128 + 128 * 64 + 64) * sizeof(float);
    cudaFuncSetAttribute(nv_main, cudaFuncAttributeMaxDynamicSharedMemorySize, (int)smem);

    nv_zero<<<(BB * KK * DD + 511) / 512, 512>>>();
    nv_main<<<dim3(NN / TT, BB), 256, smem>>>(x, cent);
    nv_fin<<<BB, 512>>>(cent, out);
}

// round 4
// speedup vs baseline: 2.5610x; 2.5610x over previous
#include <cuda_runtime.h>
#include <cstdint>
#include <math.h>

#define BB 8
#define NN 2048
#define DD 128
#define KK 64
#define TILES 16

// per-tile partials (fully rewritten every launch -> no zero kernel)
__device__ float g_Pp[BB * TILES * KK * DD];
__device__ float g_sp[BB * TILES * KK];
__device__ float g_gs[BB];

#define STR 132  // smem row stride in floats (conflict-free frag loads)

// smem float offsets
#define O_CN2 0
#define O_SSM 64
#define O_CS  128
#define O_AT  (O_CS  + KK * STR)
#define O_XS  (O_AT  + KK * STR)
#define O_XST (O_XS  + DD * STR)
#define SMF   (O_XST + DD * STR)   // 50816 floats = 203264 B

__device__ __forceinline__ uint32_t tf32r(float f) {
    uint32_t u;
    asm("cvt.rna.tf32.f32 %0, %1;" : "=r"(u) : "f"(f));
    return u;
}
__device__ __forceinline__ void mma8(float* d, const uint32_t* a, const uint32_t* b) {
    asm volatile(
        "mma.sync.aligned.m16n8k8.row.col.f32.tf32.tf32.f32 "
        "{%0,%1,%2,%3}, {%4,%5,%6,%7}, {%8,%9}, {%0,%1,%2,%3};"
        : "+f"(d[0]), "+f"(d[1]), "+f"(d[2]), "+f"(d[3])
        : "r"(a[0]), "r"(a[1]), "r"(a[2]), "r"(a[3]), "r"(b[0]), "r"(b[1]));
}

// ---------------------------------------------------------------------------
// Main: one 128-row tile per CTA. grid = (16 tiles, 8 batches), 256 threads.
// ---------------------------------------------------------------------------
__global__ __launch_bounds__(256, 1)
void nv_main(const float* __restrict__ x, const float* __restrict__ cent) {
    extern __shared__ float sm[];
    float* cn2 = sm + O_CN2;
    float* ssm = sm + O_SSM;
    float* Cs  = sm + O_CS;
    float* At  = sm + O_AT;
    float* xs  = sm + O_XS;
    float* xst = sm + O_XST;

    const int tid = threadIdx.x, w = tid >> 5, l = tid & 31;
    const int b = blockIdx.y, tile = blockIdx.x;
    const int r0 = l >> 2, c0 = l & 3;
    const int nb = w * 16;

    if (tid < 64) ssm[tid] = 0.f;
    if (tile == 0 && tid == 0) g_gs[b] = 0.f;

    // ---- phase A: load C (tf32-rounded) and raw x tile ----
    {
        const float4* c4 = (const float4*)cent;
        #pragma unroll
        for (int i = tid; i < KK * DD / 4; i += 256) {
            float4 v = c4[i];
            int k = i >> 5, d4 = (i & 31) * 4;
            float* dst = &Cs[k * STR + d4];
            dst[0] = __uint_as_float(tf32r(v.x));
            dst[1] = __uint_as_float(tf32r(v.y));
            dst[2] = __uint_as_float(tf32r(v.z));
            dst[3] = __uint_as_float(tf32r(v.w));
        }
        const float4* x4 = (const float4*)(x + ((size_t)b * NN + (size_t)tile * 128) * DD);
        #pragma unroll
        for (int i = tid; i < 128 * 32; i += 256) {
            float4 v = x4[i];
            int n = i >> 5, d4 = (i & 31) * 4;
            *(float4*)&xs[n * STR + d4] = v;
        }
    }
    __syncthreads();

    // ---- phase B: cn2[k] = ||c_k||^2 ; normalize x rows in place (+tf32 round) ----
    {
        int k = tid >> 2, q = tid & 3;
        float s = 0.f;
        #pragma unroll
        for (int j = 0; j < 8; j++) {
            float4 v = *(float4*)&Cs[k * STR + q * 32 + 4 * j];
            s += v.x * v.x + v.y * v.y + v.z * v.z + v.w * v.w;
        }
        s += __shfl_xor_sync(~0u, s, 1);
        s += __shfl_xor_sync(~0u, s, 2);
        if (q == 0) cn2[k] = s;
    }
    {
        #pragma unroll
        for (int r = w * 16; r < w * 16 + 16; r++) {
            float4 v = *(float4*)&xs[r * STR + 4 * l];
            float ss = v.x * v.x + v.y * v.y + v.z * v.z + v.w * v.w;
            #pragma unroll
            for (int o = 16; o; o >>= 1) ss += __shfl_xor_sync(~0u, ss, o);
            float ri = 1.f / fmaxf(sqrtf(ss), 1e-12f);
            v.x = __uint_as_float(tf32r(v.x * ri));
            v.y = __uint_as_float(tf32r(v.y * ri));
            v.z = __uint_as_float(tf32r(v.z * ri));
            v.w = __uint_as_float(tf32r(v.w * ri));
            *(float4*)&xs[r * STR + 4 * l] = v;
        }
    }
    __syncthreads();

    // ---- phase C: transpose xs -> xst (warp w: d-cols [16w,16w+16)) + GEMM1 ----
    {
        #pragma unroll
        for (int i = 0; i < 16; i++) {
            int d = nb + i;
            #pragma unroll
            for (int j = 0; j < 4; j++) {
                int n = l + 32 * j;
                xst[d * STR + n] = xs[n * STR + d];
            }
        }
    }

    // GEMM1: S^T[k][n] = C[k][d] * xs[n][d]^T ; warp w covers n in [16w,16w+16)
    float acc[4][2][4];
    #pragma unroll
    for (int mt = 0; mt < 4; mt++)
        #pragma unroll
        for (int nt = 0; nt < 2; nt++)
            #pragma unroll
            for (int q = 0; q < 4; q++) acc[mt][nt][q] = 0.f;

    #pragma unroll
    for (int s = 0; s < 16; s++) {
        const int col = s * 8 + c0;
        uint32_t a[4][4], bf[2][2];
        #pragma unroll
        for (int mt = 0; mt < 4; mt++) {
            const float* p = &Cs[(mt * 16 + r0) * STR + col];
            a[mt][0] = __float_as_uint(p[0]);
            a[mt][1] = __float_as_uint(p[8 * STR]);
            a[mt][2] = __float_as_uint(p[4]);
            a[mt][3] = __float_as_uint(p[8 * STR + 4]);
        }
        #pragma unroll
        for (int nt = 0; nt < 2; nt++) {
            const float* p = &xs[(nb + nt * 8 + r0) * STR + col];
            bf[nt][0] = __float_as_uint(p[0]);
            bf[nt][1] = __float_as_uint(p[4]);
        }
        #pragma unroll
        for (int mt = 0; mt < 4; mt++)
            #pragma unroll
            for (int nt = 0; nt < 2; nt++)
                mma8(acc[mt][nt], a[mt], bf[nt]);
    }

    // ---- softmax per n-column (over k=64), all within this warp ----
    // dist = cn2[k] - 2*S (||xn||^2 shift dropped: softmax shift-invariant)
    float mx[2][2] = {{-1e30f, -1e30f}, {-1e30f, -1e30f}};
    #pragma unroll
    for (int mt = 0; mt < 4; mt++) {
        float cA = cn2[mt * 16 + r0], cB = cn2[mt * 16 + r0 + 8];
        #pragma unroll
        for (int nt = 0; nt < 2; nt++) {
            acc[mt][nt][0] = cA - 2.f * acc[mt][nt][0];
            acc[mt][nt][1] = cA - 2.f * acc[mt][nt][1];
            acc[mt][nt][2] = cB - 2.f * acc[mt][nt][2];
            acc[mt][nt][3] = cB - 2.f * acc[mt][nt][3];
            mx[nt][0] = fmaxf(mx[nt][0], fmaxf(acc[mt][nt][0], acc[mt][nt][2]));
            mx[nt][1] = fmaxf(mx[nt][1], fmaxf(acc[mt][nt][1], acc[mt][nt][3]));
        }
    }
    #pragma unroll
    for (int nt = 0; nt < 2; nt++)
        #pragma unroll
        for (int pp = 0; pp < 2; pp++)
            #pragma unroll
            for (int o = 4; o <= 16; o <<= 1)
                mx[nt][pp] = fmaxf(mx[nt][pp], __shfl_xor_sync(~0u, mx[nt][pp], o));

    float sum[2][2] = {{0.f, 0.f}, {0.f, 0.f}};
    #pragma unroll
    for (int mt = 0; mt < 4; mt++)
        #pragma unroll
        for (int nt = 0; nt < 2; nt++) {
            acc[mt][nt][0] = __expf(acc[mt][nt][0] - mx[nt][0]);
            acc[mt][nt][1] = __expf(acc[mt][nt][1] - mx[nt][1]);
            acc[mt][nt][2] = __expf(acc[mt][nt][2] - mx[nt][0]);
            acc[mt][nt][3] = __expf(acc[mt][nt][3] - mx[nt][1]);
            sum[nt][0] += acc[mt][nt][0] + acc[mt][nt][2];
            sum[nt][1] += acc[mt][nt][1] + acc[mt][nt][3];
        }
    #pragma unroll
    for (int nt = 0; nt < 2; nt++)
        #pragma unroll
        for (int pp = 0; pp < 2; pp++) {
            #pragma unroll
            for (int o = 4; o <= 16; o <<= 1)
                sum[nt][pp] += __shfl_xor_sync(~0u, sum[nt][pp], o);
            sum[nt][pp] = 1.f / sum[nt][pp];
        }

    // assign values -> At[k][n] (tf32-rounded) + row sums -> ssm (atomics)
    #pragma unroll
    for (int mt = 0; mt < 4; mt++) {
        float rs0 = 0.f, rs1 = 0.f;
        #pragma unroll
        for (int nt = 0; nt < 2; nt++) {
            float a0 = acc[mt][nt][0] * sum[nt][0];
            float a1 = acc[mt][nt][1] * sum[nt][1];
            float a2 = acc[mt][nt][2] * sum[nt][0];
            float a3 = acc[mt][nt][3] * sum[nt][1];
            rs0 += a0 + a1;
            rs1 += a2 + a3;
            int rr = mt * 16 + r0, cc = nb + nt * 8 + 2 * c0;
            At[rr * STR + cc]           = __uint_as_float(tf32r(a0));
            At[rr * STR + cc + 1]       = __uint_as_float(tf32r(a1));
            At[(rr + 8) * STR + cc]     = __uint_as_float(tf32r(a2));
            At[(rr + 8) * STR + cc + 1] = __uint_as_float(tf32r(a3));
        }
        rs0 += __shfl_xor_sync(~0u, rs0, 1);
        rs0 += __shfl_xor_sync(~0u, rs0, 2);
        rs1 += __shfl_xor_sync(~0u, rs1, 1);
        rs1 += __shfl_xor_sync(~0u, rs1, 2);
        if (c0 == 0) {
            atomicAdd(&ssm[mt * 16 + r0], rs0);
            atomicAdd(&ssm[mt * 16 + r0 + 8], rs1);
        }
    }
    __syncthreads();

    // ---- phase E: GEMM2: P[k][d] = At[k][n] * xst[d][n]^T ; warp w: d in [16w,16w+16) ----
    float pc[4][2][4];
    #pragma unroll
    for (int mt = 0; mt < 4; mt++)
        #pragma unroll
        for (int nt = 0; nt < 2; nt++)
            #pragma unroll
            for (int q = 0; q < 4; q++) pc[mt][nt][q] = 0.f;

    #pragma unroll
    for (int s = 0; s < 16; s++) {
        const int col = s * 8 + c0;
        uint32_t a[4][4], bf[2][2];
        #pragma unroll
        for (int mt = 0; mt < 4; mt++) {
            const float* p = &At[(mt * 16 + r0) * STR + col];
            a[mt][0] = __float_as_uint(p[0]);
            a[mt][1] = __float_as_uint(p[8 * STR]);
            a[mt][2] = __float_as_uint(p[4]);
            a[mt][3] = __float_as_uint(p[8 * STR + 4]);
        }
        #pragma unroll
        for (int nt = 0; nt < 2; nt++) {
            const float* p = &xst[(nb + nt * 8 + r0) * STR + col];
            bf[nt][0] = __float_as_uint(p[0]);
            bf[nt][1] = __float_as_uint(p[4]);
        }
        #pragma unroll
        for (int mt = 0; mt < 4; mt++)
            #pragma unroll
            for (int nt = 0; nt < 2; nt++)
                mma8(pc[mt][nt], a[mt], bf[nt]);
    }

    // store per-tile partials
    float* Pb = g_Pp + (size_t)(b * TILES + tile) * KK * DD;
    #pragma unroll
    for (int mt = 0; mt < 4; mt++)
        #pragma unroll
        for (int nt = 0; nt < 2; nt++) {
            int rr = mt * 16 + r0, dd2 = nb + nt * 8 + 2 * c0;
            *(float2*)&Pb[rr * DD + dd2]       = make_float2(pc[mt][nt][0], pc[mt][nt][1]);
            *(float2*)&Pb[(rr + 8) * DD + dd2] = make_float2(pc[mt][nt][2], pc[mt][nt][3]);
        }
    if (tid < 64) g_sp[(b * TILES + tile) * KK + tid] = ssm[tid];
}

// ---------------------------------------------------------------------------
// fin1: grid (b=8, kg=8), 256 thr. warp per k: reduce tiles, v = P - s*c,
// intra-normalize, write; accumulate true global sumsq into g_gs[b].
// ---------------------------------------------------------------------------
__global__ __launch_bounds__(256, 1)
void nv_fin1(const float* __restrict__ cent, float* __restrict__ out) {
    const int b = blockIdx.x, kg = blockIdx.y;
    const int tid = threadIdx.x, l = tid & 31;
    const int k = kg * 8 + (tid >> 5);

    float4 a = make_float4(0.f, 0.f, 0.f, 0.f);
    #pragma unroll
    for (int t = 0; t < TILES; t++) {
        const float4 v = *(const float4*)&g_Pp[((size_t)(b * TILES + t) * KK + k) * DD + 4 * l];
        a.x += v.x; a.y += v.y; a.z += v.z; a.w += v.w;
    }
    float sv = (l < 16) ? g_sp[(b * TILES + l) * KK + k] : 0.f;
    #pragma unroll
    for (int o = 8; o; o >>= 1) sv += __shfl_xor_sync(~0u, sv, o);
    float sk = __shfl_sync(~0u, sv, 0);

    const float4 c = *(const float4*)&cent[k * DD + 4 * l];
    float4 v = make_float4(a.x - sk * c.x, a.y - sk * c.y, a.z - sk * c.z, a.w - sk * c.w);
    float ss = v.x * v.x + v.y * v.y + v.z * v.z + v.w * v.w;
    #pragma unroll
    for (int o = 16; o; o >>= 1) ss += __shfl_xor_sync(~0u, ss, o);
    float ri = 1.f / fmaxf(sqrtf(ss), 1e-12f);
    v.x *= ri; v.y *= ri; v.z *= ri; v.w *= ri;
    *(float4*)&out[(size_t)b * KK * DD + k * DD + 4 * l] = v;
    if (l == 0) atomicAdd(&g_gs[b], ss * ri * ri);
}

// ---------------------------------------------------------------------------
// fin2: global rescale by 1/||.||
// ---------------------------------------------------------------------------
__global__ __launch_bounds__(256, 1)
void nv_fin2(float* __restrict__ out) {
    const int b = blockIdx.x;
    const float gi = 1.f / fmaxf(sqrtf(g_gs[b]), 1e-12f);
    float4* o = (float4*)(out + (size_t)b * KK * DD);
    #pragma unroll
    for (int i = threadIdx.x; i < KK * DD / 4; i += 256) {
        float4 v = o[i];
        v.x *= gi; v.y *= gi; v.z *= gi; v.w *= gi;
        o[i] = v;
    }
}

// ---------------------------------------------------------------------------
extern "C" void kernel_launch(void* const* d_in, const int* in_sizes, int n_in,
                              void* d_out, int out_size) {
    (void)in_sizes; (void)n_in; (void)out_size;
    const float* x    = (const float*)d_in[0];
    const float* cent = (const float*)d_in[1];
    float* out        = (float*)d_out;

    cudaFuncSetAttribute(nv_main, cudaFuncAttributeMaxDynamicSharedMemorySize,
                         (int)(SMF * sizeof(float)));
    nv_main<<<dim3(TILES, BB), 256, SMF * sizeof(float)>>>(x, cent);
    nv_fin1<<<dim3(BB, 8), 256>>>(cent, out);
    nv_fin2<<<BB, 256>>>(out);
}

// round 5
// speedup vs baseline: 2.8047x; 1.0952x over previous
#include <cuda_runtime.h>
#include <cstdint>
#include <math.h>

#define BB 8
#define NN 2048
#define DD 128
#define KK 64
#define TILES 16

// per-tile partials (fully rewritten every launch -> no zero kernel)
__device__ float g_Pp[BB * TILES * KK * DD];
__device__ float g_sp[BB * TILES * KK];

#define STR 132  // smem row stride in floats (conflict-free frag loads)

// smem float offsets
#define O_CN2 0
#define O_SSM 64
#define O_CS  128
#define O_AT  (O_CS + KK * STR)
#define O_XS  (O_AT + KK * STR)
#define SMF   (O_XS + DD * STR)   // 33920 floats = 135680 B

__device__ __forceinline__ uint32_t tf32r(float f) {
    uint32_t u;
    asm("cvt.rna.tf32.f32 %0, %1;" : "=r"(u) : "f"(f));
    return u;
}
__device__ __forceinline__ void mma8(float* d, const uint32_t* a, const uint32_t* b) {
    asm volatile(
        "mma.sync.aligned.m16n8k8.row.col.f32.tf32.tf32.f32 "
        "{%0,%1,%2,%3}, {%4,%5,%6,%7}, {%8,%9}, {%0,%1,%2,%3};"
        : "+f"(d[0]), "+f"(d[1]), "+f"(d[2]), "+f"(d[3])
        : "r"(a[0]), "r"(a[1]), "r"(a[2]), "r"(a[3]), "r"(b[0]), "r"(b[1]));
}

// ---------------------------------------------------------------------------
// Main: one 128-row tile per CTA. grid = (16 tiles, 8 batches), 512 threads.
// Warp w owns 8 output columns: n in [8w,8w+8) for GEMM1/softmax,
// d in [8w,8w+8) for GEMM2.
// ---------------------------------------------------------------------------
__global__ __launch_bounds__(512, 1)
void nv_main(const float* __restrict__ x, const float* __restrict__ cent) {
    extern __shared__ float sm[];
    float* cn2 = sm + O_CN2;
    float* ssm = sm + O_SSM;
    float* Cs  = sm + O_CS;
    float* At  = sm + O_AT;
    float* xs  = sm + O_XS;

    const int tid = threadIdx.x, w = tid >> 5, l = tid & 31;
    const int b = blockIdx.y, tile = blockIdx.x;
    const int r0 = l >> 2, c0 = l & 3;
    const int nb = w * 8;

    if (tid < 64) ssm[tid] = 0.f;

    // ---- phase A: load C (tf32-rounded) and raw x tile ----
    {
        const float4* c4 = (const float4*)cent;
        #pragma unroll
        for (int i = tid; i < KK * DD / 4; i += 512) {
            float4 v = c4[i];
            int k = i >> 5, d4 = (i & 31) * 4;
            float* dst = &Cs[k * STR + d4];
            dst[0] = __uint_as_float(tf32r(v.x));
            dst[1] = __uint_as_float(tf32r(v.y));
            dst[2] = __uint_as_float(tf32r(v.z));
            dst[3] = __uint_as_float(tf32r(v.w));
        }
        const float4* x4 = (const float4*)(x + ((size_t)b * NN + (size_t)tile * 128) * DD);
        #pragma unroll
        for (int i = tid; i < 128 * 32; i += 512) {
            float4 v = x4[i];
            int n = i >> 5, d4 = (i & 31) * 4;
            *(float4*)&xs[n * STR + d4] = v;
        }
    }
    __syncthreads();

    // ---- phase B: cn2[k] = ||c_k||^2 ; L2-normalize x rows in place + tf32 round ----
    {
        int k = tid >> 3, q = tid & 7;
        float s = 0.f;
        #pragma unroll
        for (int j = 0; j < 4; j++) {
            float4 v = *(float4*)&Cs[k * STR + q * 16 + 4 * j];
            s += v.x * v.x + v.y * v.y + v.z * v.z + v.w * v.w;
        }
        s += __shfl_xor_sync(~0u, s, 1);
        s += __shfl_xor_sync(~0u, s, 2);
        s += __shfl_xor_sync(~0u, s, 4);
        if (q == 0) cn2[k] = s;
    }
    {
        #pragma unroll
        for (int r = w * 8; r < w * 8 + 8; r++) {
            float4 v = *(float4*)&xs[r * STR + 4 * l];
            float ss = v.x * v.x + v.y * v.y + v.z * v.z + v.w * v.w;
            #pragma unroll
            for (int o = 16; o; o >>= 1) ss += __shfl_xor_sync(~0u, ss, o);
            float ri = 1.f / fmaxf(sqrtf(ss), 1e-12f);
            v.x = __uint_as_float(tf32r(v.x * ri));
            v.y = __uint_as_float(tf32r(v.y * ri));
            v.z = __uint_as_float(tf32r(v.z * ri));
            v.w = __uint_as_float(tf32r(v.w * ri));
            *(float4*)&xs[r * STR + 4 * l] = v;
        }
    }
    __syncthreads();

    // ---- GEMM1: S^T[k][n] = C[k][d] * xn[n][d]^T ; warp w: n in [8w,8w+8) ----
    float acc[4][4];
    #pragma unroll
    for (int mt = 0; mt < 4; mt++)
        #pragma unroll
        for (int q = 0; q < 4; q++) acc[mt][q] = 0.f;

    #pragma unroll
    for (int s = 0; s < 16; s++) {
        const int col = s * 8 + c0;
        uint32_t a[4][4], bf[2];
        #pragma unroll
        for (int mt = 0; mt < 4; mt++) {
            const float* p = &Cs[(mt * 16 + r0) * STR + col];
            a[mt][0] = __float_as_uint(p[0]);
            a[mt][1] = __float_as_uint(p[8 * STR]);
            a[mt][2] = __float_as_uint(p[4]);
            a[mt][3] = __float_as_uint(p[8 * STR + 4]);
        }
        {
            const float* p = &xs[(nb + r0) * STR + col];
            bf[0] = __float_as_uint(p[0]);
            bf[1] = __float_as_uint(p[4]);
        }
        #pragma unroll
        for (int mt = 0; mt < 4; mt++) mma8(acc[mt], a[mt], bf);
    }

    // ---- softmax per n-column over k=64 (within warp) ----
    // dist = cn2[k] - 2*S (||xn||^2 shift dropped: softmax shift-invariant)
    float mx0 = -1e30f, mx1 = -1e30f;
    #pragma unroll
    for (int mt = 0; mt < 4; mt++) {
        float cA = cn2[mt * 16 + r0], cB = cn2[mt * 16 + r0 + 8];
        acc[mt][0] = cA - 2.f * acc[mt][0];
        acc[mt][1] = cA - 2.f * acc[mt][1];
        acc[mt][2] = cB - 2.f * acc[mt][2];
        acc[mt][3] = cB - 2.f * acc[mt][3];
        mx0 = fmaxf(mx0, fmaxf(acc[mt][0], acc[mt][2]));
        mx1 = fmaxf(mx1, fmaxf(acc[mt][1], acc[mt][3]));
    }
    #pragma unroll
    for (int o = 4; o <= 16; o <<= 1) {
        mx0 = fmaxf(mx0, __shfl_xor_sync(~0u, mx0, o));
        mx1 = fmaxf(mx1, __shfl_xor_sync(~0u, mx1, o));
    }
    float s0 = 0.f, s1 = 0.f;
    #pragma unroll
    for (int mt = 0; mt < 4; mt++) {
        acc[mt][0] = __expf(acc[mt][0] - mx0);
        acc[mt][1] = __expf(acc[mt][1] - mx1);
        acc[mt][2] = __expf(acc[mt][2] - mx0);
        acc[mt][3] = __expf(acc[mt][3] - mx1);
        s0 += acc[mt][0] + acc[mt][2];
        s1 += acc[mt][1] + acc[mt][3];
    }
    #pragma unroll
    for (int o = 4; o <= 16; o <<= 1) {
        s0 += __shfl_xor_sync(~0u, s0, o);
        s1 += __shfl_xor_sync(~0u, s1, o);
    }
    s0 = 1.f / s0;
    s1 = 1.f / s1;

    // assign -> At[k][n] (tf32-rounded) + row sums -> ssm
    #pragma unroll
    for (int mt = 0; mt < 4; mt++) {
        float a0 = acc[mt][0] * s0, a1 = acc[mt][1] * s1;
        float a2 = acc[mt][2] * s0, a3 = acc[mt][3] * s1;
        float rs0 = a0 + a1, rs1 = a2 + a3;
        int rr = mt * 16 + r0, cc = nb + 2 * c0;
        At[rr * STR + cc]           = __uint_as_float(tf32r(a0));
        At[rr * STR + cc + 1]       = __uint_as_float(tf32r(a1));
        At[(rr + 8) * STR + cc]     = __uint_as_float(tf32r(a2));
        At[(rr + 8) * STR + cc + 1] = __uint_as_float(tf32r(a3));
        rs0 += __shfl_xor_sync(~0u, rs0, 1);
        rs0 += __shfl_xor_sync(~0u, rs0, 2);
        rs1 += __shfl_xor_sync(~0u, rs1, 1);
        rs1 += __shfl_xor_sync(~0u, rs1, 2);
        if (c0 == 0) {
            atomicAdd(&ssm[rr], rs0);
            atomicAdd(&ssm[rr + 8], rs1);
        }
    }
    __syncthreads();

    // ---- GEMM2: P[k][d] = At[k][n] * Xn[n][d] ; warp w: d in [8w,8w+8) ----
    // B operand read directly from row-major xs with swapped indices
    // (bank = 4*c0 + r0: conflict-free) -> no transpose buffer needed.
    float pc[4][4];
    #pragma unroll
    for (int mt = 0; mt < 4; mt++)
        #pragma unroll
        for (int q = 0; q < 4; q++) pc[mt][q] = 0.f;

    #pragma unroll
    for (int s = 0; s < 16; s++) {
        const int col = s * 8 + c0;
        uint32_t a[4][4], bf[2];
        #pragma unroll
        for (int mt = 0; mt < 4; mt++) {
            const float* p = &At[(mt * 16 + r0) * STR + col];
            a[mt][0] = __float_as_uint(p[0]);
            a[mt][1] = __float_as_uint(p[8 * STR]);
            a[mt][2] = __float_as_uint(p[4]);
            a[mt][3] = __float_as_uint(p[8 * STR + 4]);
        }
        bf[0] = __float_as_uint(xs[(size_t)col * STR + nb + r0]);
        bf[1] = __float_as_uint(xs[(size_t)(col + 4) * STR + nb + r0]);
        #pragma unroll
        for (int mt = 0; mt < 4; mt++) mma8(pc[mt], a[mt], bf);
    }

    // store per-tile partials
    float* Pb = g_Pp + (size_t)(b * TILES + tile) * KK * DD;
    #pragma unroll
    for (int mt = 0; mt < 4; mt++) {
        int rr = mt * 16 + r0, dd2 = nb + 2 * c0;
        *(float2*)&Pb[rr * DD + dd2]       = make_float2(pc[mt][0], pc[mt][1]);
        *(float2*)&Pb[(rr + 8) * DD + dd2] = make_float2(pc[mt][2], pc[mt][3]);
    }
    if (tid < 64) g_sp[(b * TILES + tile) * KK + tid] = ssm[tid];
}

// ---------------------------------------------------------------------------
// fin: grid (b=8, kg=8), 256 thr, warp per k. Reduce tiles, v = P - s*c,
// intra-normalize, apply exact global scale 1/8 (64 unit k-vectors =>
// global norm = 8), write out. Single finalize launch.
// ---------------------------------------------------------------------------
__global__ __launch_bounds__(256, 1)
void nv_fin(const float* __restrict__ cent, float* __restrict__ out) {
    const int b = blockIdx.x, kg = blockIdx.y;
    const int tid = threadIdx.x, l = tid & 31;
    const int k = kg * 8 + (tid >> 5);

    float4 a = make_float4(0.f, 0.f, 0.f, 0.f);
    #pragma unroll
    for (int t = 0; t < TILES; t++) {
        const float4 v = *(const float4*)&g_Pp[((size_t)(b * TILES + t) * KK + k) * DD + 4 * l];
        a.x += v.x; a.y += v.y; a.z += v.z; a.w += v.w;
    }
    float sv = (l < 16) ? g_sp[(b * TILES + l) * KK + k] : 0.f;
    #pragma unroll
    for (int o = 8; o; o >>= 1) sv += __shfl_xor_sync(~0u, sv, o);
    float sk = __shfl_sync(~0u, sv, 0);

    const float4 c = *(const float4*)&cent[k * DD + 4 * l];
    float4 v = make_float4(a.x - sk * c.x, a.y - sk * c.y, a.z - sk * c.z, a.w - sk * c.w);
    float ss = v.x * v.x + v.y * v.y + v.z * v.z + v.w * v.w;
    #pragma unroll
    for (int o = 16; o; o >>= 1) ss += __shfl_xor_sync(~0u, ss, o);
    float sc = 0.125f / fmaxf(sqrtf(ss), 1e-12f);
    v.x *= sc; v.y *= sc; v.z *= sc; v.w *= sc;
    *(float4*)&out[(size_t)b * KK * DD + k * DD + 4 * l] = v;
}

// ---------------------------------------------------------------------------
extern "C" void kernel_launch(void* const* d_in, const int* in_sizes, int n_in,
                              void* d_out, int out_size) {
    (void)in_sizes; (void)n_in; (void)out_size;
    const float* x    = (const float*)d_in[0];
    const float* cent = (const float*)d_in[1];
    float* out        = (float*)d_out;

    cudaFuncSetAttribute(nv_main, cudaFuncAttributeMaxDynamicSharedMemorySize,
                         (int)(SMF * sizeof(float)));
    nv_main<<<dim3(TILES, BB), 512, SMF * sizeof(float)>>>(x, cent);
    nv_fin<<<dim3(BB, 8), 256>>>(cent, out);
}